// round 6
// baseline (speedup 1.0000x reference)
#include <cuda_runtime.h>

#define MGRAPHS 8192
#define NODES   64
#define DH      128
#define DX      128

// 4 MB scratch for HA = h @ a  (device global: allocation-free, allowed)
__device__ float g_HA[MGRAPHS * DX];

// ---------- packed f32x2 helpers (sm_100+ FFMA2 path) ----------
static __device__ __forceinline__ unsigned long long pack2_dup(float v) {
    unsigned long long r;
    asm("mov.b64 %0, {%1, %1};" : "=l"(r) : "f"(v));
    return r;
}
static __device__ __forceinline__ unsigned long long fma2(unsigned long long a,
                                                          unsigned long long b,
                                                          unsigned long long c) {
    unsigned long long d;
    asm("fma.rn.f32x2 %0, %1, %2, %3;" : "=l"(d) : "l"(a), "l"(b), "l"(c));
    return d;
}
static __device__ __forceinline__ float2 unpack2(unsigned long long v) {
    float lo, hi;
    asm("mov.b64 {%0, %1}, %2;" : "=f"(lo), "=f"(hi) : "l"(v));
    float2 f; f.x = lo; f.y = hi; return f;
}

// ============================================================================
// Kernel 1: HA[g][d] = sum_k h[g][k] * a[k][d]
// 128 blocks x 256 threads; each block computes 64 graph rows.
// a chunk (32x128) + h chunk (64x32, padded stride 36) staged in smem.
// Thread t computes 4 graphs x 8 dims, accumulated as 16 f32x2 pairs.
// ============================================================================
__global__ void __launch_bounds__(256) ha_kernel(const float* __restrict__ h,
                                                 const float* __restrict__ a) {
    __shared__ float a_s[32 * DX];     // 16 KB
    __shared__ float h_s[64 * 36];     // 9 KB (row stride 36 floats: 16B-aligned, conflict-free)

    const int t     = threadIdx.x;
    const int gbase = blockIdx.x * 64;
    const int dcol  = (t & 15) * 8;    // dims dcol..dcol+7
    const int grow  = (t >> 4) * 4;    // local graphs grow..grow+3

    unsigned long long acc[4][4];
#pragma unroll
    for (int j = 0; j < 4; j++)
#pragma unroll
        for (int p = 0; p < 4; p++) acc[j][p] = 0ULL;

    for (int kc = 0; kc < 4; kc++) {
        __syncthreads();  // protect smem from previous chunk's readers

        // stage a[kc*32 .. +31][0..127]  (1024 float4)
        const float4* a4  = (const float4*)(a + kc * 32 * DX);
        float4*       as4 = (float4*)a_s;
#pragma unroll
        for (int q = 0; q < 4; q++) as4[t + 256 * q] = a4[t + 256 * q];

        // stage h[gbase..gbase+63][kc*32 .. +31]  (512 float4)
#pragma unroll
        for (int q = 0; q < 2; q++) {
            int idx = t + 256 * q;
            int row = idx >> 3, c4 = idx & 7;
            float4 hv = *(const float4*)(h + (size_t)(gbase + row) * DH + kc * 32 + c4 * 4);
            *(float4*)(&h_s[row * 36 + c4 * 4]) = hv;
        }
        __syncthreads();

#pragma unroll
        for (int k = 0; k < 32; k++) {
            // two LDS.128 -> four f32x2 pairs of a[k][dcol..dcol+7]
            const ulonglong2* ap = (const ulonglong2*)(a_s + k * DX + dcol);
            ulonglong2 A0 = ap[0];
            ulonglong2 A1 = ap[1];
#pragma unroll
            for (int j = 0; j < 4; j++) {
                unsigned long long hp = pack2_dup(h_s[(grow + j) * 36 + k]);
                acc[j][0] = fma2(hp, A0.x, acc[j][0]);
                acc[j][1] = fma2(hp, A0.y, acc[j][1]);
                acc[j][2] = fma2(hp, A1.x, acc[j][2]);
                acc[j][3] = fma2(hp, A1.y, acc[j][3]);
            }
        }
    }

#pragma unroll
    for (int j = 0; j < 4; j++) {
        float* dst = g_HA + (size_t)(gbase + grow + j) * DX + dcol;
#pragma unroll
        for (int p = 0; p < 4; p++) {
            float2 v = unpack2(acc[j][p]);
            *(float2*)(dst + p * 2) = v;
        }
    }
}

// ============================================================================
// Kernel 2: per-graph segment softmax attention, single pass over x.
// One CTA (256 threads) per graph. Thread t keeps 8 float4s of x in registers:
//   float4 index j = t + 256k  ->  node = w + 8k (w = warp),  dims = 4l (l = lane)
// e via warp butterfly, z via 8-entry smem sum, out via 4 KB smem reduction.
// ============================================================================
__global__ void __launch_bounds__(256) attn_kernel(const float* __restrict__ x,
                                                   float* __restrict__ out) {
    __shared__ float4 red[8][32];
    __shared__ float  zw[8];

    const int g = blockIdx.x;
    const int t = threadIdx.x;
    const int w = t >> 5, l = t & 31;

    // one contiguous 32 KB block per CTA, MLP=8
    const float4* x4 = (const float4*)x + (size_t)g * (NODES * DX / 4);
    float4 xv[8];
#pragma unroll
    for (int k = 0; k < 8; k++) xv[k] = x4[t + 256 * k];

    const float4 hav = ((const float4*)g_HA)[g * (DX / 4) + l];

    float att[8];
    float zsum = 0.0f;
#pragma unroll
    for (int k = 0; k < 8; k++) {
        float p = xv[k].x * hav.x + xv[k].y * hav.y + xv[k].z * hav.z + xv[k].w * hav.w;
#pragma unroll
        for (int o = 16; o; o >>= 1) p += __shfl_xor_sync(0xffffffffu, p, o);
        float ex = __expf(p);   // unstabilized, faithful to reference
        att[k] = ex;
        zsum  += ex;
    }
    if (l == 0) zw[w] = zsum;   // zsum is lane-uniform after the butterfly
    __syncthreads();

    float z = zw[0] + zw[1] + zw[2] + zw[3] + zw[4] + zw[5] + zw[6] + zw[7];
    float inv = 1.0f / z;

    float4 o4 = make_float4(0.f, 0.f, 0.f, 0.f);
#pragma unroll
    for (int k = 0; k < 8; k++) {
        float aw = att[k] * inv;
        o4.x += aw * xv[k].x;
        o4.y += aw * xv[k].y;
        o4.z += aw * xv[k].z;
        o4.w += aw * xv[k].w;
    }
    red[w][l] = o4;
    __syncthreads();

    if (t < 32) {
        float4 s = red[0][t];
#pragma unroll
        for (int j = 1; j < 8; j++) {
            float4 r = red[j][t];
            s.x += r.x; s.y += r.y; s.z += r.z; s.w += r.w;
        }
        ((float4*)out)[g * (DX / 4) + t] = s;
    }
}

// ============================================================================
// inputs (metadata order): h (8192x128 f32), x (524288x128 f32),
//                          a (128x128 f32), batch_num_nodes (8192 i32, all 64)
// output: out (8192x128 f32)
// ============================================================================
extern "C" void kernel_launch(void* const* d_in, const int* in_sizes, int n_in,
                              void* d_out, int out_size) {
    const float* h = (const float*)d_in[0];
    const float* x = (const float*)d_in[1];
    const float* a = (const float*)d_in[2];
    float* out = (float*)d_out;
    (void)in_sizes; (void)n_in; (void)out_size;

    ha_kernel<<<MGRAPHS / 64, 256>>>(h, a);
    attn_kernel<<<MGRAPHS, 256>>>(x, out);
}

// round 8
// speedup vs baseline: 1.2309x; 1.2309x over previous
#include <cuda_runtime.h>

#define MGRAPHS 8192
#define NODES   64
#define DH      128
#define DX      128

// 4 MB scratch for HA = h @ a  (device global: allocation-free, allowed)
__device__ float g_HA[MGRAPHS * DX];

// ---------- packed f32x2 helpers (sm_100+ FFMA2 path) ----------
static __device__ __forceinline__ unsigned long long pack2_dup(float v) {
    unsigned long long r;
    asm("mov.b64 %0, {%1, %1};" : "=l"(r) : "f"(v));
    return r;
}
static __device__ __forceinline__ unsigned long long fma2(unsigned long long a,
                                                          unsigned long long b,
                                                          unsigned long long c) {
    unsigned long long d;
    asm("fma.rn.f32x2 %0, %1, %2, %3;" : "=l"(d) : "l"(a), "l"(b), "l"(c));
    return d;
}
static __device__ __forceinline__ float2 unpack2(unsigned long long v) {
    float lo, hi;
    asm("mov.b64 {%0, %1}, %2;" : "=f"(lo), "=f"(hi) : "l"(v));
    float2 f; f.x = lo; f.y = hi; return f;
}

// ============================================================================
// Kernel 1: HA[g][d] = sum_k h[g][k] * a[k][d]
// 256 blocks x 256 threads; each block computes 32 graph rows.
// Full a (64 KB) staged once in smem with a lo/hi permutation so the per-k
// LDS.128 reads are bank-conflict-free:
//   original dim d = g*8+u  ->  (u<4) ? float g*4+u : 64 + g*4 + (u-4)
// Lane group g (= t&15) then reads floats [g*4..g*4+3] and [64+g*4..+3]:
// within an 8-lane phase these hit 8 distinct bank quads.
// h tile hoisted into registers in k-chunks of 16 (broadcast LDS.128).
// Thread t computes 2 graphs x 8 dims, accumulated as 8 f32x2 pairs.
// ============================================================================
__global__ void __launch_bounds__(256) ha_kernel(const float* __restrict__ h,
                                                 const float* __restrict__ a) {
    // signal PDL dependents as early as possible (attn's x loads don't need us)
    asm volatile("griddepcontrol.launch_dependents;");

    __shared__ float a_s[DH * DX];   // 64 KB, permuted rows
    __shared__ float h_s[32 * 132];  // 16.5 KB (stride 132 floats, conflict-free)

    const int t     = threadIdx.x;
    const int gbase = blockIdx.x * 32;

    // stage a: 4096 float4, permuted lo/hi halves
    const float4* a4  = (const float4*)a;
    float4*       as4 = (float4*)a_s;
#pragma unroll
    for (int q = 0; q < 16; q++) {
        int idx = t + 256 * q;
        int k   = idx >> 5;        // row
        int c   = idx & 31;        // float4 column
        int g   = c >> 1, u = c & 1;
        int col4 = u ? (16 + g) : g;
        as4[k * 32 + col4] = a4[idx];
    }
    // stage h: 32 rows x 128 floats = 1024 float4
#pragma unroll
    for (int q = 0; q < 4; q++) {
        int idx = t + 256 * q;
        int row = idx >> 5, c4 = idx & 31;
        float4 hv = *(const float4*)(h + (size_t)(gbase + row) * DH + c4 * 4);
        *(float4*)(&h_s[row * 132 + c4 * 4]) = hv;
    }
    __syncthreads();

    const int g    = t & 15;        // dim group: dims g*8 .. g*8+7
    const int grow = (t >> 4) * 2;  // local graphs grow, grow+1

    unsigned long long acc[2][4];
#pragma unroll
    for (int j = 0; j < 2; j++)
#pragma unroll
        for (int p = 0; p < 4; p++) acc[j][p] = 0ULL;

#pragma unroll 1
    for (int kc = 0; kc < 8; kc++) {   // k chunks of 16
        float hreg[2][16];
#pragma unroll
        for (int j = 0; j < 2; j++)
#pragma unroll
            for (int q = 0; q < 4; q++)
                *(float4*)&hreg[j][q * 4] =
                    *(const float4*)&h_s[(grow + j) * 132 + kc * 16 + q * 4];

#pragma unroll
        for (int kk = 0; kk < 16; kk++) {
            const float* base = a_s + (kc * 16 + kk) * DX;
            ulonglong2 A0 = *(const ulonglong2*)(base + g * 4);        // dims g*8..+3
            ulonglong2 A1 = *(const ulonglong2*)(base + 64 + g * 4);   // dims g*8+4..+7
#pragma unroll
            for (int j = 0; j < 2; j++) {
                unsigned long long hp = pack2_dup(hreg[j][kk]);
                acc[j][0] = fma2(hp, A0.x, acc[j][0]);
                acc[j][1] = fma2(hp, A0.y, acc[j][1]);
                acc[j][2] = fma2(hp, A1.x, acc[j][2]);
                acc[j][3] = fma2(hp, A1.y, acc[j][3]);
            }
        }
    }

#pragma unroll
    for (int j = 0; j < 2; j++) {
        float* dst = g_HA + (size_t)(gbase + grow + j) * DX + g * 8;
        float2 v0 = unpack2(acc[j][0]), v1 = unpack2(acc[j][1]);
        float2 v2 = unpack2(acc[j][2]), v3 = unpack2(acc[j][3]);
        *(float4*)(dst)     = make_float4(v0.x, v0.y, v1.x, v1.y);
        *(float4*)(dst + 4) = make_float4(v2.x, v2.y, v3.x, v3.y);
    }
}

// ============================================================================
// Kernel 2: per-graph segment softmax attention, single pass over x.
// One CTA (512 threads) per graph. Thread t keeps 4 float4s of x in registers:
//   float4 index j = t + 512k  ->  node = w + 16k (w = warp),  dims = 4l.
// x loads are issued BEFORE griddepcontrol.wait so they overlap ha_kernel
// under PDL; g_HA is read only after the wait.
// ============================================================================
__global__ void __launch_bounds__(512, 3) attn_kernel(const float* __restrict__ x,
                                                      float* __restrict__ out) {
    __shared__ float4 red[16][32];   // 8 KB
    __shared__ float4 zwv[4];        // 16 warp z-partials

    const int g = blockIdx.x;
    const int t = threadIdx.x;
    const int w = t >> 5, l = t & 31;

    // one contiguous 32 KB block per CTA; 4 front-batched LDG.128 per thread
    const float4* x4 = (const float4*)x + (size_t)g * (NODES * DX / 4);
    float4 xv[4];
#pragma unroll
    for (int k = 0; k < 4; k++) xv[k] = x4[t + 512 * k];

    // PDL: wait for ha_kernel's g_HA writes (no-op if launched without PDL)
    asm volatile("griddepcontrol.wait;" ::: "memory");

    const float4 hav = ((const float4*)g_HA)[g * (DX / 4) + l];

    float att[4];
    float zsum = 0.0f;
#pragma unroll
    for (int k = 0; k < 4; k++) {
        float p = xv[k].x * hav.x + xv[k].y * hav.y + xv[k].z * hav.z + xv[k].w * hav.w;
#pragma unroll
        for (int o = 16; o; o >>= 1) p += __shfl_xor_sync(0xffffffffu, p, o);
        float ex = __expf(p);   // unstabilized, faithful to reference
        att[k] = ex;
        zsum  += ex;
    }
    if (l == 0) ((float*)zwv)[w] = zsum;   // lane-uniform after butterfly
    __syncthreads();

    float4 za = zwv[0], zb = zwv[1], zc = zwv[2], zd = zwv[3];
    float z = (za.x + za.y + za.z + za.w) + (zb.x + zb.y + zb.z + zb.w) +
              (zc.x + zc.y + zc.z + zc.w) + (zd.x + zd.y + zd.z + zd.w);
    float inv = 1.0f / z;

    float4 o4 = make_float4(0.f, 0.f, 0.f, 0.f);
#pragma unroll
    for (int k = 0; k < 4; k++) {
        float aw = att[k] * inv;
        o4.x += aw * xv[k].x;
        o4.y += aw * xv[k].y;
        o4.z += aw * xv[k].z;
        o4.w += aw * xv[k].w;
    }
    red[w][l] = o4;
    __syncthreads();

    if (t < 32) {
        float4 s = red[0][t];
#pragma unroll
        for (int j = 1; j < 16; j++) {
            float4 r = red[j][t];
            s.x += r.x; s.y += r.y; s.z += r.z; s.w += r.w;
        }
        ((float4*)out)[g * (DX / 4) + t] = s;
    }
}

// ============================================================================
// inputs (metadata order): h (8192x128 f32), x (524288x128 f32),
//                          a (128x128 f32), batch_num_nodes (8192 i32, all 64)
// output: out (8192x128 f32)
// ============================================================================
extern "C" void kernel_launch(void* const* d_in, const int* in_sizes, int n_in,
                              void* d_out, int out_size) {
    const float* h = (const float*)d_in[0];
    const float* x = (const float*)d_in[1];
    const float* a = (const float*)d_in[2];
    float* out = (float*)d_out;
    (void)in_sizes; (void)n_in; (void)out_size;

    ha_kernel<<<MGRAPHS / 32, 256>>>(h, a);

    // attn with programmatic dependent launch (overlaps x loads with ha)
    cudaLaunchConfig_t cfg = {};
    cfg.gridDim  = dim3(MGRAPHS, 1, 1);
    cfg.blockDim = dim3(512, 1, 1);
    cfg.dynamicSmemBytes = 0;
    cfg.stream = 0;
    cudaLaunchAttribute attr[1];
    attr[0].id = cudaLaunchAttributeProgrammaticStreamSerialization;
    attr[0].val.programmaticStreamSerializationAllowed = 1;
    cfg.attrs = attr;
    cfg.numAttrs = 1;
    cudaError_t e = cudaLaunchKernelEx(&cfg, attn_kernel, x, out);
    if (e != cudaSuccess) {
        (void)cudaGetLastError();  // clear; fall back to plain serialized launch
        attn_kernel<<<MGRAPHS, 512>>>(x, out);
    }
}